// round 1
// baseline (speedup 1.0000x reference)
#include <cuda_runtime.h>
#include <math_constants.h>

#define B_   2
#define T_   2048
#define D_   1024
#define H_   16
#define DK_  64
#define DM_  256
#define D2_  2048

// ---------------- scratch (device globals; no allocation allowed) ----------
__device__ float g_hcat[(size_t)B_ * T_ * D2_];   // (B*T, 2D)  33.5 MB
__device__ float g_Q   [(size_t)B_ * T_ * D_];    // 16.8 MB
__device__ float g_K   [(size_t)B_ * T_ * D_];
__device__ float g_V   [(size_t)B_ * T_ * D_];
__device__ float g_bias[(size_t)B_ * T_ * T_];    // (B, T, T)  33.5 MB
__device__ float g_O   [(size_t)B_ * T_ * D_];

// ---------------- hx transpose: Hx (B,D,T,1) -> g_hcat[:, 0:D] -------------
__global__ void transpose_hx_kernel(const float* __restrict__ Hx) {
    __shared__ float tile[32][33];
    int b  = blockIdx.z;
    int d0 = blockIdx.y * 32;
    int t0 = blockIdx.x * 32;
    #pragma unroll
    for (int yy = threadIdx.y; yy < 32; yy += 8)
        tile[yy][threadIdx.x] = Hx[((size_t)(b * D_ + d0 + yy)) * T_ + t0 + threadIdx.x];
    __syncthreads();
    #pragma unroll
    for (int yy = threadIdx.y; yy < 32; yy += 8)
        g_hcat[((size_t)(b * T_ + t0 + yy)) * D2_ + d0 + threadIdx.x] = tile[threadIdx.x][yy];
}

// ---------------- Hf copy into g_hcat[:, D:2D] ------------------------------
__global__ void copy_hf_kernel(const float4* __restrict__ Hf) {
    int idx = blockIdx.x * blockDim.x + threadIdx.x;   // over B*T*D/4
    if (idx >= B_ * T_ * (D_ / 4)) return;
    int row  = idx / (D_ / 4);
    int col4 = idx % (D_ / 4);
    float4 v = Hf[idx];
    *reinterpret_cast<float4*>(&g_hcat[(size_t)row * D2_ + D_ + col4 * 4]) = v;
}

// ---------------- GEMM: C[M,N] = A[M,K] * W[N,K]^T + bias[N] ----------------
// Tile 128x64, BK=32, 256 threads, 8x4 per thread. All dims multiples of tile.
__global__ void __launch_bounds__(256) gemm_nt_kernel(
    const float* __restrict__ A, int lda,
    const float* __restrict__ W,
    const float* __restrict__ bias,
    float* __restrict__ C, int ldc, int Kdim)
{
    __shared__ float As[32][132];   // [k][m], padded (2-way max conflict on store)
    __shared__ float Ws[32][68];    // [k][n]

    const int tid = threadIdx.x;
    const int ty  = tid >> 4;       // 0..15 -> 8 rows each
    const int tx  = tid & 15;       // 0..15 -> 4 cols each
    const size_t mBase = (size_t)blockIdx.y * 128;
    const int    nBase = blockIdx.x * 64;

    const float* Ap = A + mBase * lda;
    const float* Wp = W + (size_t)nBase * Kdim;

    float acc[8][4];
    #pragma unroll
    for (int r = 0; r < 8; r++)
        #pragma unroll
        for (int c = 0; c < 4; c++) acc[r][c] = 0.f;

    for (int k0 = 0; k0 < Kdim; k0 += 32) {
        #pragma unroll
        for (int i = tid; i < 128 * 8; i += 256) {       // 128 rows x 8 float4
            int r  = i >> 3;
            int kc = (i & 7) << 2;
            float4 v = *reinterpret_cast<const float4*>(&Ap[(size_t)r * lda + k0 + kc]);
            As[kc + 0][r] = v.x; As[kc + 1][r] = v.y;
            As[kc + 2][r] = v.z; As[kc + 3][r] = v.w;
        }
        #pragma unroll
        for (int i = tid; i < 64 * 8; i += 256) {        // 64 rows x 8 float4
            int r  = i >> 3;
            int kc = (i & 7) << 2;
            float4 v = *reinterpret_cast<const float4*>(&Wp[(size_t)r * Kdim + k0 + kc]);
            Ws[kc + 0][r] = v.x; Ws[kc + 1][r] = v.y;
            Ws[kc + 2][r] = v.z; Ws[kc + 3][r] = v.w;
        }
        __syncthreads();
        #pragma unroll 8
        for (int kk = 0; kk < 32; kk++) {
            float4 a0 = *reinterpret_cast<const float4*>(&As[kk][ty * 8]);
            float4 a1 = *reinterpret_cast<const float4*>(&As[kk][ty * 8 + 4]);
            float4 wv = *reinterpret_cast<const float4*>(&Ws[kk][tx * 4]);
            float aa[8] = {a0.x, a0.y, a0.z, a0.w, a1.x, a1.y, a1.z, a1.w};
            float ww[4] = {wv.x, wv.y, wv.z, wv.w};
            #pragma unroll
            for (int r = 0; r < 8; r++)
                #pragma unroll
                for (int c = 0; c < 4; c++)
                    acc[r][c] = fmaf(aa[r], ww[c], acc[r][c]);
        }
        __syncthreads();
    }

    float4 bv = *reinterpret_cast<const float4*>(&bias[nBase + tx * 4]);
    #pragma unroll
    for (int r = 0; r < 8; r++) {
        float4 ov = make_float4(acc[r][0] + bv.x, acc[r][1] + bv.y,
                                acc[r][2] + bv.z, acc[r][3] + bv.w);
        *reinterpret_cast<float4*>(&C[(mBase + ty * 8 + r) * ldc + nBase + tx * 4]) = ov;
    }
}

// ---------------- flash attention with additive bias ------------------------
__device__ __forceinline__ float rmax16(float v) {
    v = fmaxf(v, __shfl_xor_sync(0xffffffffu, v, 8, 16));
    v = fmaxf(v, __shfl_xor_sync(0xffffffffu, v, 4, 16));
    v = fmaxf(v, __shfl_xor_sync(0xffffffffu, v, 2, 16));
    v = fmaxf(v, __shfl_xor_sync(0xffffffffu, v, 1, 16));
    return v;
}
__device__ __forceinline__ float rsum16(float v) {
    v += __shfl_xor_sync(0xffffffffu, v, 8, 16);
    v += __shfl_xor_sync(0xffffffffu, v, 4, 16);
    v += __shfl_xor_sync(0xffffffffu, v, 2, 16);
    v += __shfl_xor_sync(0xffffffffu, v, 1, 16);
    return v;
}

#define APAD 68
#define ATTN_SMEM (4 * 64 * APAD * (int)sizeof(float))   // 69632 B

__global__ void __launch_bounds__(256) attn_kernel() {
    extern __shared__ float sm[];
    float (*Qs)[APAD] = (float(*)[APAD])(sm);              // Qs[dk][q]
    float (*Ks)[APAD] = (float(*)[APAD])(sm + 64 * APAD);  // Ks[dk][k]
    float (*Vs)[APAD] = (float(*)[APAD])(sm + 2 * 64 * APAD); // Vs[k][dk]
    float (*Ps)[APAD] = (float(*)[APAD])(sm + 3 * 64 * APAD); // Ps[q][k]

    const int tid = threadIdx.x;
    const int ty  = tid >> 4;   // q micro-row group (4 rows)
    const int tx  = tid & 15;   // k / dk micro-col group (4 cols)
    const int b   = blockIdx.z;
    const int h   = blockIdx.y;
    const int q0  = blockIdx.x * 64;

    const float* __restrict__ Qg = g_Q + (size_t)b * T_ * D_ + (size_t)h * DK_;
    const float* __restrict__ Kg = g_K + (size_t)b * T_ * D_ + (size_t)h * DK_;
    const float* __restrict__ Vg = g_V + (size_t)b * T_ * D_ + (size_t)h * DK_;
    const float* __restrict__ Bg = g_bias + ((size_t)b * T_ + q0) * T_;

    // Q tile (64 q x 64 dk) -> Qs[dk][q]
    #pragma unroll
    for (int i = tid; i < 64 * 16; i += 256) {
        int r  = i >> 4;
        int c4 = (i & 15) << 2;
        float4 v = *reinterpret_cast<const float4*>(&Qg[(size_t)(q0 + r) * D_ + c4]);
        Qs[c4 + 0][r] = v.x; Qs[c4 + 1][r] = v.y;
        Qs[c4 + 2][r] = v.z; Qs[c4 + 3][r] = v.w;
    }

    float m[4], l[4], o[4][4];
    #pragma unroll
    for (int r = 0; r < 4; r++) {
        m[r] = -CUDART_INF_F; l[r] = 0.f;
        #pragma unroll
        for (int c = 0; c < 4; c++) o[r][c] = 0.f;
    }

    for (int k0 = 0; k0 < T_; k0 += 64) {
        __syncthreads();   // also covers Q-load on first iter
        #pragma unroll
        for (int i = tid; i < 64 * 16; i += 256) {
            int r  = i >> 4;
            int c4 = (i & 15) << 2;
            float4 v = *reinterpret_cast<const float4*>(&Kg[(size_t)(k0 + r) * D_ + c4]);
            Ks[c4 + 0][r] = v.x; Ks[c4 + 1][r] = v.y;
            Ks[c4 + 2][r] = v.z; Ks[c4 + 3][r] = v.w;
            float4 u = *reinterpret_cast<const float4*>(&Vg[(size_t)(k0 + r) * D_ + c4]);
            *reinterpret_cast<float4*>(&Vs[r][c4]) = u;
        }
        __syncthreads();

        // S = Q K^T   (4x4 micro tile per thread)
        float s[4][4];
        #pragma unroll
        for (int r = 0; r < 4; r++)
            #pragma unroll
            for (int c = 0; c < 4; c++) s[r][c] = 0.f;

        #pragma unroll 8
        for (int d = 0; d < 64; d++) {
            float4 qv = *reinterpret_cast<const float4*>(&Qs[d][ty * 4]);
            float4 kv = *reinterpret_cast<const float4*>(&Ks[d][tx * 4]);
            float qa[4] = {qv.x, qv.y, qv.z, qv.w};
            float ka[4] = {kv.x, kv.y, kv.z, kv.w};
            #pragma unroll
            for (int r = 0; r < 4; r++)
                #pragma unroll
                for (int c = 0; c < 4; c++)
                    s[r][c] = fmaf(qa[r], ka[c], s[r][c]);
        }

        // scale + bias + online softmax
        #pragma unroll
        for (int r = 0; r < 4; r++) {
            float4 bv = *reinterpret_cast<const float4*>(
                &Bg[(size_t)(ty * 4 + r) * T_ + k0 + tx * 4]);
            s[r][0] = fmaf(s[r][0], 0.125f, bv.x);
            s[r][1] = fmaf(s[r][1], 0.125f, bv.y);
            s[r][2] = fmaf(s[r][2], 0.125f, bv.z);
            s[r][3] = fmaf(s[r][3], 0.125f, bv.w);

            float mx = fmaxf(fmaxf(s[r][0], s[r][1]), fmaxf(s[r][2], s[r][3]));
            mx = rmax16(mx);
            float mnew = fmaxf(m[r], mx);
            float corr = __expf(m[r] - mnew);
            s[r][0] = __expf(s[r][0] - mnew);
            s[r][1] = __expf(s[r][1] - mnew);
            s[r][2] = __expf(s[r][2] - mnew);
            s[r][3] = __expf(s[r][3] - mnew);
            float rs = rsum16(s[r][0] + s[r][1] + s[r][2] + s[r][3]);
            l[r] = l[r] * corr + rs;
            m[r] = mnew;
            #pragma unroll
            for (int c = 0; c < 4; c++) o[r][c] *= corr;
            *reinterpret_cast<float4*>(&Ps[ty * 4 + r][tx * 4]) =
                make_float4(s[r][0], s[r][1], s[r][2], s[r][3]);
        }
        __syncthreads();

        // O += P @ V
        #pragma unroll 8
        for (int j = 0; j < 64; j++) {
            float4 vv = *reinterpret_cast<const float4*>(&Vs[j][tx * 4]);
            float p0 = Ps[ty * 4 + 0][j];
            float p1 = Ps[ty * 4 + 1][j];
            float p2 = Ps[ty * 4 + 2][j];
            float p3 = Ps[ty * 4 + 3][j];
            o[0][0] = fmaf(p0, vv.x, o[0][0]); o[0][1] = fmaf(p0, vv.y, o[0][1]);
            o[0][2] = fmaf(p0, vv.z, o[0][2]); o[0][3] = fmaf(p0, vv.w, o[0][3]);
            o[1][0] = fmaf(p1, vv.x, o[1][0]); o[1][1] = fmaf(p1, vv.y, o[1][1]);
            o[1][2] = fmaf(p1, vv.z, o[1][2]); o[1][3] = fmaf(p1, vv.w, o[1][3]);
            o[2][0] = fmaf(p2, vv.x, o[2][0]); o[2][1] = fmaf(p2, vv.y, o[2][1]);
            o[2][2] = fmaf(p2, vv.z, o[2][2]); o[2][3] = fmaf(p2, vv.w, o[2][3]);
            o[3][0] = fmaf(p3, vv.x, o[3][0]); o[3][1] = fmaf(p3, vv.y, o[3][1]);
            o[3][2] = fmaf(p3, vv.z, o[3][2]); o[3][3] = fmaf(p3, vv.w, o[3][3]);
        }
    }

    #pragma unroll
    for (int r = 0; r < 4; r++) {
        float inv = 1.0f / l[r];
        float4 ov = make_float4(o[r][0] * inv, o[r][1] * inv,
                                o[r][2] * inv, o[r][3] * inv);
        *reinterpret_cast<float4*>(
            &g_O[((size_t)b * T_ + q0 + ty * 4 + r) * D_ + h * DK_ + tx * 4]) = ov;
    }
}

// ---------------- launch ----------------------------------------------------
extern "C" void kernel_launch(void* const* d_in, const int* in_sizes, int n_in,
                              void* d_out, int out_size) {
    const float* Hx = (const float*)d_in[0];
    const float* Hf = (const float*)d_in[1];
    const float* Gm = (const float*)d_in[2];
    const float* Wg = (const float*)d_in[3];
    const float* bg = (const float*)d_in[4];
    const float* Wq = (const float*)d_in[5];
    const float* bq = (const float*)d_in[6];
    const float* Wk = (const float*)d_in[7];
    const float* bk = (const float*)d_in[8];
    const float* Wv = (const float*)d_in[9];
    const float* bv = (const float*)d_in[10];
    const float* Wo = (const float*)d_in[11];
    const float* bo = (const float*)d_in[12];
    float* out = (float*)d_out;

    float *hcat, *Q, *K, *V, *bias, *O;
    cudaGetSymbolAddress((void**)&hcat, g_hcat);
    cudaGetSymbolAddress((void**)&Q,    g_Q);
    cudaGetSymbolAddress((void**)&K,    g_K);
    cudaGetSymbolAddress((void**)&V,    g_V);
    cudaGetSymbolAddress((void**)&bias, g_bias);
    cudaGetSymbolAddress((void**)&O,    g_O);

    // 1) build hcat = [hx | Hf]
    transpose_hx_kernel<<<dim3(T_ / 32, D_ / 32, B_), dim3(32, 8)>>>(Hx);
    copy_hf_kernel<<<(B_ * T_ * (D_ / 4) + 255) / 256, 256>>>((const float4*)Hf);

    // 2) projections (M = B*T = 4096 -> grid.y = 32)
    gemm_nt_kernel<<<dim3(D_ / 64, 32), 256>>>(hcat, D2_, Wq, bq, Q, D_, D2_);
    gemm_nt_kernel<<<dim3(D_ / 64, 32), 256>>>(hcat, D2_, Wk, bk, K, D_, D2_);
    gemm_nt_kernel<<<dim3(D_ / 64, 32), 256>>>(hcat, D2_, Wv, bv, V, D_, D_);
    // 3) bias = Gm @ Wg^T + bg : (B*T, T)
    gemm_nt_kernel<<<dim3(T_ / 64, 32), 256>>>(Gm, DM_, Wg, bg, bias, T_, DM_);

    // 4) attention
    cudaFuncSetAttribute(attn_kernel, cudaFuncAttributeMaxDynamicSharedMemorySize,
                         ATTN_SMEM);
    attn_kernel<<<dim3(T_ / 64, H_, B_), 256, ATTN_SMEM>>>();

    // 5) output projection
    gemm_nt_kernel<<<dim3(D_ / 64, 32), 256>>>(O, D_, Wo, bo, out, D_, D_);
}

// round 2
// speedup vs baseline: 2.1735x; 2.1735x over previous
#include <cuda_runtime.h>
#include <math_constants.h>
#include <cstdint>

#define B_   2
#define T_   2048
#define D_   1024
#define H_   16
#define DK_  64
#define DM_  256
#define D2_  2048

// ---------------- scratch (device globals; no allocation allowed) ----------
__device__ float g_hcat[(size_t)B_ * T_ * D2_];
__device__ float g_Q   [(size_t)B_ * T_ * D_];
__device__ float g_K   [(size_t)B_ * T_ * D_];
__device__ float g_V   [(size_t)B_ * T_ * D_];
__device__ float g_bias[(size_t)B_ * T_ * T_];
__device__ float g_O   [(size_t)B_ * T_ * D_];

// ---------------- tf32 helpers ---------------------------------------------
__device__ __forceinline__ uint32_t f2tf(float x) {
    uint32_t u; asm("cvt.rna.tf32.f32 %0, %1;" : "=r"(u) : "f"(x)); return u;
}
__device__ __forceinline__ void mma_tf32(float* c, const uint32_t* a, const uint32_t* b) {
    asm volatile("mma.sync.aligned.m16n8k8.row.col.f32.tf32.tf32.f32 "
        "{%0,%1,%2,%3}, {%4,%5,%6,%7}, {%8,%9}, {%0,%1,%2,%3};\n"
        : "+f"(c[0]), "+f"(c[1]), "+f"(c[2]), "+f"(c[3])
        : "r"(a[0]), "r"(a[1]), "r"(a[2]), "r"(a[3]), "r"(b[0]), "r"(b[1]));
}

// ---------------- hx transpose: Hx (B,D,T,1) -> g_hcat[:, 0:D] -------------
__global__ void transpose_hx_kernel(const float* __restrict__ Hx) {
    __shared__ float tile[32][33];
    int b  = blockIdx.z;
    int d0 = blockIdx.y * 32;
    int t0 = blockIdx.x * 32;
    #pragma unroll
    for (int yy = threadIdx.y; yy < 32; yy += 8)
        tile[yy][threadIdx.x] = Hx[((size_t)(b * D_ + d0 + yy)) * T_ + t0 + threadIdx.x];
    __syncthreads();
    #pragma unroll
    for (int yy = threadIdx.y; yy < 32; yy += 8)
        g_hcat[((size_t)(b * T_ + t0 + yy)) * D2_ + d0 + threadIdx.x] = tile[threadIdx.x][yy];
}

// ---------------- Hf copy into g_hcat[:, D:2D] ------------------------------
__global__ void copy_hf_kernel(const float4* __restrict__ Hf) {
    int idx = blockIdx.x * blockDim.x + threadIdx.x;
    if (idx >= B_ * T_ * (D_ / 4)) return;
    int row  = idx / (D_ / 4);
    int col4 = idx % (D_ / 4);
    float4 v = Hf[idx];
    *reinterpret_cast<float4*>(&g_hcat[(size_t)row * D2_ + D_ + col4 * 4]) = v;
}

// ---------------- tf32 tensor-core GEMM: C = A[M,K] * W[N,K]^T + bias -------
// Block 128x128x32, 256 threads = 8 warps (2 m x 4 n), warp tile 64x32.
#define GBM 128
#define GBN 128
#define GBK 32
#define GLD 132   // 132 % 32 == 4 -> <=2-way conflicts on fragment loads

__global__ void __launch_bounds__(256) gemm_tf32_kernel(
    const float* __restrict__ A, int lda,
    const float* __restrict__ W,
    const float* __restrict__ bias,
    float* __restrict__ C, int ldc, int Kdim)
{
    __shared__ uint32_t As[GBK * GLD];   // [k][m] tf32 bits
    __shared__ uint32_t Ws[GBK * GLD];   // [k][n] tf32 bits

    const int tid  = threadIdx.x;
    const int lane = tid & 31;
    const int warp = tid >> 5;
    const int g    = lane >> 2;
    const int tq   = lane & 3;
    const int wm   = warp & 1;
    const int wn   = warp >> 1;
    const size_t mBase = (size_t)blockIdx.y * GBM;
    const int    nBase = blockIdx.x * GBN;

    const float* Ap = A + mBase * lda;
    const float* Wp = W + (size_t)nBase * Kdim;

    float acc[4][4][4];
    #pragma unroll
    for (int mt = 0; mt < 4; mt++)
        #pragma unroll
        for (int nt = 0; nt < 4; nt++)
            #pragma unroll
            for (int e = 0; e < 4; e++) acc[mt][nt][e] = 0.f;

    float4 ra[4], rw[4];

    // prologue: load tile 0
    #pragma unroll
    for (int j = 0; j < 4; j++) {
        int i = tid + 256 * j;
        int r = i >> 3, kc = (i & 7) << 2;
        ra[j] = *reinterpret_cast<const float4*>(&Ap[(size_t)r * lda + kc]);
        rw[j] = *reinterpret_cast<const float4*>(&Wp[(size_t)r * Kdim + kc]);
    }
    #pragma unroll
    for (int j = 0; j < 4; j++) {
        int i = tid + 256 * j;
        int r = i >> 3, kc = (i & 7) << 2;
        As[(kc + 0) * GLD + r] = f2tf(ra[j].x);
        As[(kc + 1) * GLD + r] = f2tf(ra[j].y);
        As[(kc + 2) * GLD + r] = f2tf(ra[j].z);
        As[(kc + 3) * GLD + r] = f2tf(ra[j].w);
        Ws[(kc + 0) * GLD + r] = f2tf(rw[j].x);
        Ws[(kc + 1) * GLD + r] = f2tf(rw[j].y);
        Ws[(kc + 2) * GLD + r] = f2tf(rw[j].z);
        Ws[(kc + 3) * GLD + r] = f2tf(rw[j].w);
    }
    __syncthreads();

    for (int k0 = 0; k0 < Kdim; k0 += GBK) {
        bool has_next = (k0 + GBK) < Kdim;
        if (has_next) {
            #pragma unroll
            for (int j = 0; j < 4; j++) {
                int i = tid + 256 * j;
                int r = i >> 3, kc = (i & 7) << 2;
                ra[j] = *reinterpret_cast<const float4*>(&Ap[(size_t)r * lda + k0 + GBK + kc]);
                rw[j] = *reinterpret_cast<const float4*>(&Wp[(size_t)r * Kdim + k0 + GBK + kc]);
            }
        }
        // compute 32-deep k on smem tile
        #pragma unroll
        for (int s = 0; s < 4; s++) {
            uint32_t af[4][4], bf[4][2];
            #pragma unroll
            for (int mt = 0; mt < 4; mt++) {
                int m = wm * 64 + mt * 16 + g;
                af[mt][0] = As[(s * 8 + tq)     * GLD + m];
                af[mt][1] = As[(s * 8 + tq)     * GLD + m + 8];
                af[mt][2] = As[(s * 8 + tq + 4) * GLD + m];
                af[mt][3] = As[(s * 8 + tq + 4) * GLD + m + 8];
            }
            #pragma unroll
            for (int nt = 0; nt < 4; nt++) {
                int n = wn * 32 + nt * 8 + g;
                bf[nt][0] = Ws[(s * 8 + tq)     * GLD + n];
                bf[nt][1] = Ws[(s * 8 + tq + 4) * GLD + n];
            }
            #pragma unroll
            for (int mt = 0; mt < 4; mt++)
                #pragma unroll
                for (int nt = 0; nt < 4; nt++)
                    mma_tf32(acc[mt][nt], af[mt], bf[nt]);
        }
        if (has_next) {
            __syncthreads();
            #pragma unroll
            for (int j = 0; j < 4; j++) {
                int i = tid + 256 * j;
                int r = i >> 3, kc = (i & 7) << 2;
                As[(kc + 0) * GLD + r] = f2tf(ra[j].x);
                As[(kc + 1) * GLD + r] = f2tf(ra[j].y);
                As[(kc + 2) * GLD + r] = f2tf(ra[j].z);
                As[(kc + 3) * GLD + r] = f2tf(ra[j].w);
                Ws[(kc + 0) * GLD + r] = f2tf(rw[j].x);
                Ws[(kc + 1) * GLD + r] = f2tf(rw[j].y);
                Ws[(kc + 2) * GLD + r] = f2tf(rw[j].z);
                Ws[(kc + 3) * GLD + r] = f2tf(rw[j].w);
            }
            __syncthreads();
        }
    }

    // epilogue
    #pragma unroll
    for (int nt = 0; nt < 4; nt++) {
        int col = nBase + wn * 32 + nt * 8 + 2 * tq;
        float2 bv = *reinterpret_cast<const float2*>(&bias[col]);
        #pragma unroll
        for (int mt = 0; mt < 4; mt++) {
            size_t row = mBase + wm * 64 + mt * 16 + g;
            float2 v0 = make_float2(acc[mt][nt][0] + bv.x, acc[mt][nt][1] + bv.y);
            float2 v1 = make_float2(acc[mt][nt][2] + bv.x, acc[mt][nt][3] + bv.y);
            *reinterpret_cast<float2*>(&C[row * ldc + col])       = v0;
            *reinterpret_cast<float2*>(&C[(row + 8) * ldc + col]) = v1;
        }
    }
}

// ---------------- tf32 flash attention with additive bias -------------------
#define ALD 68
#define ATTN_SMEM ((3 * 64 * ALD + 4 * 16 * ALD) * (int)sizeof(uint32_t))  // 69632

__global__ void __launch_bounds__(128) attn_tf32_kernel() {
    extern __shared__ uint32_t sm[];
    uint32_t* Qs = sm;                 // [64][ALD] tf32 bits
    uint32_t* Ks = sm + 64 * ALD;      // [64][ALD]
    uint32_t* Vs = sm + 2 * 64 * ALD;  // [64][ALD]
    uint32_t* Ps = sm + 3 * 64 * ALD;  // 4 warps x [16][ALD]

    const int tid  = threadIdx.x;
    const int lane = tid & 31;
    const int warp = tid >> 5;
    const int g    = lane >> 2;
    const int tq   = lane & 3;
    const int b    = blockIdx.z;
    const int h    = blockIdx.y;
    const int q0   = blockIdx.x * 64;

    const float* __restrict__ Qg = g_Q + (size_t)b * T_ * D_ + (size_t)h * DK_;
    const float* __restrict__ Kg = g_K + (size_t)b * T_ * D_ + (size_t)h * DK_;
    const float* __restrict__ Vg = g_V + (size_t)b * T_ * D_ + (size_t)h * DK_;
    const float* __restrict__ Bg = g_bias + ((size_t)b * T_ + q0) * T_;

    // stage Q (64 x 64) as tf32
    #pragma unroll
    for (int i = tid; i < 64 * 16; i += 128) {
        int r = i >> 4, c4 = (i & 15) << 2;
        float4 v = *reinterpret_cast<const float4*>(&Qg[(size_t)(q0 + r) * D_ + c4]);
        Qs[r * ALD + c4 + 0] = f2tf(v.x);
        Qs[r * ALD + c4 + 1] = f2tf(v.y);
        Qs[r * ALD + c4 + 2] = f2tf(v.z);
        Qs[r * ALD + c4 + 3] = f2tf(v.w);
    }
    __syncthreads();

    // Q fragments register-resident for all 8 k-steps
    uint32_t qa[8][4];
    {
        int base = (warp * 16 + g) * ALD;
        #pragma unroll
        for (int s = 0; s < 8; s++) {
            qa[s][0] = Qs[base + 8 * s + tq];
            qa[s][1] = Qs[base + 8 * ALD + 8 * s + tq];
            qa[s][2] = Qs[base + 8 * s + tq + 4];
            qa[s][3] = Qs[base + 8 * ALD + 8 * s + tq + 4];
        }
    }

    float o[8][4];
    #pragma unroll
    for (int nt = 0; nt < 8; nt++)
        #pragma unroll
        for (int e = 0; e < 4; e++) o[nt][e] = 0.f;
    float m0 = -CUDART_INF_F, m1 = -CUDART_INF_F, l0 = 0.f, l1 = 0.f;

    uint32_t* Pw = Ps + warp * 16 * ALD;

    for (int k0 = 0; k0 < T_; k0 += 64) {
        __syncthreads();
        #pragma unroll
        for (int i = tid; i < 64 * 16; i += 128) {
            int r = i >> 4, c4 = (i & 15) << 2;
            float4 kv = *reinterpret_cast<const float4*>(&Kg[(size_t)(k0 + r) * D_ + c4]);
            Ks[r * ALD + c4 + 0] = f2tf(kv.x);
            Ks[r * ALD + c4 + 1] = f2tf(kv.y);
            Ks[r * ALD + c4 + 2] = f2tf(kv.z);
            Ks[r * ALD + c4 + 3] = f2tf(kv.w);
            float4 vv = *reinterpret_cast<const float4*>(&Vg[(size_t)(k0 + r) * D_ + c4]);
            Vs[r * ALD + c4 + 0] = f2tf(vv.x);
            Vs[r * ALD + c4 + 1] = f2tf(vv.y);
            Vs[r * ALD + c4 + 2] = f2tf(vv.z);
            Vs[r * ALD + c4 + 3] = f2tf(vv.w);
        }
        __syncthreads();

        // S = Q K^T
        float sf[8][4];
        #pragma unroll
        for (int nt = 0; nt < 8; nt++) {
            sf[nt][0] = sf[nt][1] = sf[nt][2] = sf[nt][3] = 0.f;
            #pragma unroll
            for (int s = 0; s < 8; s++) {
                uint32_t bb[2];
                bb[0] = Ks[(nt * 8 + g) * ALD + 8 * s + tq];
                bb[1] = Ks[(nt * 8 + g) * ALD + 8 * s + tq + 4];
                mma_tf32(sf[nt], qa[s], bb);
            }
        }

        // scale + bias, row max
        const float* Brow0 = Bg + (size_t)(warp * 16 + g) * T_ + k0;
        const float* Brow1 = Brow0 + 8 * T_;
        float mx0 = -CUDART_INF_F, mx1 = -CUDART_INF_F;
        #pragma unroll
        for (int nt = 0; nt < 8; nt++) {
            float2 b0v = *reinterpret_cast<const float2*>(&Brow0[nt * 8 + 2 * tq]);
            float2 b1v = *reinterpret_cast<const float2*>(&Brow1[nt * 8 + 2 * tq]);
            sf[nt][0] = fmaf(sf[nt][0], 0.125f, b0v.x);
            sf[nt][1] = fmaf(sf[nt][1], 0.125f, b0v.y);
            sf[nt][2] = fmaf(sf[nt][2], 0.125f, b1v.x);
            sf[nt][3] = fmaf(sf[nt][3], 0.125f, b1v.y);
            mx0 = fmaxf(mx0, fmaxf(sf[nt][0], sf[nt][1]));
            mx1 = fmaxf(mx1, fmaxf(sf[nt][2], sf[nt][3]));
        }
        mx0 = fmaxf(mx0, __shfl_xor_sync(0xffffffffu, mx0, 1));
        mx0 = fmaxf(mx0, __shfl_xor_sync(0xffffffffu, mx0, 2));
        mx1 = fmaxf(mx1, __shfl_xor_sync(0xffffffffu, mx1, 1));
        mx1 = fmaxf(mx1, __shfl_xor_sync(0xffffffffu, mx1, 2));

        float mn0 = fmaxf(m0, mx0), mn1 = fmaxf(m1, mx1);
        float c0 = __expf(m0 - mn0), c1 = __expf(m1 - mn1);
        float rs0 = 0.f, rs1 = 0.f;
        #pragma unroll
        for (int nt = 0; nt < 8; nt++) {
            float p0 = __expf(sf[nt][0] - mn0);
            float p1 = __expf(sf[nt][1] - mn0);
            float p2 = __expf(sf[nt][2] - mn1);
            float p3 = __expf(sf[nt][3] - mn1);
            rs0 += p0 + p1;
            rs1 += p2 + p3;
            uint2 u0 = make_uint2(f2tf(p0), f2tf(p1));
            uint2 u1 = make_uint2(f2tf(p2), f2tf(p3));
            *reinterpret_cast<uint2*>(&Pw[g * ALD + nt * 8 + 2 * tq])       = u0;
            *reinterpret_cast<uint2*>(&Pw[(g + 8) * ALD + nt * 8 + 2 * tq]) = u1;
        }
        rs0 += __shfl_xor_sync(0xffffffffu, rs0, 1);
        rs0 += __shfl_xor_sync(0xffffffffu, rs0, 2);
        rs1 += __shfl_xor_sync(0xffffffffu, rs1, 1);
        rs1 += __shfl_xor_sync(0xffffffffu, rs1, 2);
        l0 = l0 * c0 + rs0;
        l1 = l1 * c1 + rs1;
        m0 = mn0; m1 = mn1;
        #pragma unroll
        for (int nt = 0; nt < 8; nt++) {
            o[nt][0] *= c0; o[nt][1] *= c0;
            o[nt][2] *= c1; o[nt][3] *= c1;
        }
        __syncwarp();

        // O += P V
        #pragma unroll
        for (int s = 0; s < 8; s++) {
            uint32_t pa[4];
            pa[0] = Pw[g * ALD + 8 * s + tq];
            pa[1] = Pw[(g + 8) * ALD + 8 * s + tq];
            pa[2] = Pw[g * ALD + 8 * s + tq + 4];
            pa[3] = Pw[(g + 8) * ALD + 8 * s + tq + 4];
            #pragma unroll
            for (int nt = 0; nt < 8; nt++) {
                uint32_t bb[2];
                bb[0] = Vs[(8 * s + tq) * ALD + nt * 8 + g];
                bb[1] = Vs[(8 * s + tq + 4) * ALD + nt * 8 + g];
                mma_tf32(o[nt], pa, bb);
            }
        }
        __syncwarp();
    }

    // epilogue
    float inv0 = 1.0f / l0, inv1 = 1.0f / l1;
    float* Og = g_O + (size_t)b * T_ * D_ + (size_t)h * DK_;
    size_t r0 = (size_t)q0 + warp * 16 + g;
    #pragma unroll
    for (int nt = 0; nt < 8; nt++) {
        int col = nt * 8 + 2 * tq;
        float2 v0 = make_float2(o[nt][0] * inv0, o[nt][1] * inv0);
        float2 v1 = make_float2(o[nt][2] * inv1, o[nt][3] * inv1);
        *reinterpret_cast<float2*>(&Og[r0 * D_ + col])       = v0;
        *reinterpret_cast<float2*>(&Og[(r0 + 8) * D_ + col]) = v1;
    }
}

// ---------------- launch ----------------------------------------------------
extern "C" void kernel_launch(void* const* d_in, const int* in_sizes, int n_in,
                              void* d_out, int out_size) {
    const float* Hx = (const float*)d_in[0];
    const float* Hf = (const float*)d_in[1];
    const float* Gm = (const float*)d_in[2];
    const float* Wg = (const float*)d_in[3];
    const float* bg = (const float*)d_in[4];
    const float* Wq = (const float*)d_in[5];
    const float* bq = (const float*)d_in[6];
    const float* Wk = (const float*)d_in[7];
    const float* bk = (const float*)d_in[8];
    const float* Wv = (const float*)d_in[9];
    const float* bv = (const float*)d_in[10];
    const float* Wo = (const float*)d_in[11];
    const float* bo = (const float*)d_in[12];
    float* out = (float*)d_out;

    float *hcat, *Q, *K, *V, *bias, *O;
    cudaGetSymbolAddress((void**)&hcat, g_hcat);
    cudaGetSymbolAddress((void**)&Q,    g_Q);
    cudaGetSymbolAddress((void**)&K,    g_K);
    cudaGetSymbolAddress((void**)&V,    g_V);
    cudaGetSymbolAddress((void**)&bias, g_bias);
    cudaGetSymbolAddress((void**)&O,    g_O);

    // 1) build hcat = [hx | Hf]
    transpose_hx_kernel<<<dim3(T_ / 32, D_ / 32, B_), dim3(32, 8)>>>(Hx);
    copy_hf_kernel<<<(B_ * T_ * (D_ / 4) + 255) / 256, 256>>>((const float4*)Hf);

    // 2) projections (M = B*T = 4096 -> grid.y = 32)
    gemm_tf32_kernel<<<dim3(D_ / GBN, 32), 256>>>(hcat, D2_, Wq, bq, Q, D_, D2_);
    gemm_tf32_kernel<<<dim3(D_ / GBN, 32), 256>>>(hcat, D2_, Wk, bk, K, D_, D2_);
    gemm_tf32_kernel<<<dim3(D_ / GBN, 32), 256>>>(hcat, D2_, Wv, bv, V, D_, D_);
    // 3) bias = Gm @ Wg^T + bg : (B*T, T)
    gemm_tf32_kernel<<<dim3(T_ / GBN, 32), 256>>>(Gm, DM_, Wg, bg, bias, T_, DM_);

    // 4) attention
    cudaFuncSetAttribute(attn_tf32_kernel, cudaFuncAttributeMaxDynamicSharedMemorySize,
                         ATTN_SMEM);
    attn_tf32_kernel<<<dim3(T_ / 64, H_, B_), 128, ATTN_SMEM>>>();

    // 5) output projection
    gemm_tf32_kernel<<<dim3(D_ / GBN, 32), 256>>>(O, D_, Wo, bo, out, D_, D_);
}

// round 4
// speedup vs baseline: 3.0615x; 1.4086x over previous
#include <cuda_runtime.h>
#include <math_constants.h>
#include <cstdint>

#define B_   2
#define T_   2048
#define D_   1024
#define H_   16
#define DK_  64
#define DM_  256
#define D2_  2048

// ---------------- scratch (device globals; no allocation allowed) ----------
__device__ float g_hcat[(size_t)B_ * T_ * D2_];
__device__ float g_Q   [(size_t)B_ * T_ * D_];
__device__ float g_K   [(size_t)B_ * T_ * D_];
__device__ float g_V   [(size_t)B_ * T_ * D_];
__device__ float g_bias[(size_t)B_ * T_ * T_];
__device__ float g_O   [(size_t)B_ * T_ * D_];

// ---------------- helpers ----------------------------------------------------
__device__ __forceinline__ uint32_t f2tf(float x) {
    uint32_t u; asm("cvt.rna.tf32.f32 %0, %1;" : "=r"(u) : "f"(x)); return u;
}
__device__ __forceinline__ void mma_tf32(float* c, const uint32_t* a, const uint32_t* b) {
    asm volatile("mma.sync.aligned.m16n8k8.row.col.f32.tf32.tf32.f32 "
        "{%0,%1,%2,%3}, {%4,%5,%6,%7}, {%8,%9}, {%0,%1,%2,%3};\n"
        : "+f"(c[0]), "+f"(c[1]), "+f"(c[2]), "+f"(c[3])
        : "r"(a[0]), "r"(a[1]), "r"(a[2]), "r"(a[3]), "r"(b[0]), "r"(b[1]));
}
__device__ __forceinline__ uint32_t smem_u32(const void* p) {
    uint32_t a;
    asm("{ .reg .u64 t; cvta.to.shared.u64 t, %1; cvt.u32.u64 %0, t; }" : "=r"(a) : "l"(p));
    return a;
}
__device__ __forceinline__ void cp_async16(uint32_t dst, const void* src) {
    asm volatile("cp.async.cg.shared.global [%0], [%1], 16;"
                 :: "r"(dst), "l"(src) : "memory");
}

// ---------------- hx transpose: Hx (B,D,T,1) -> g_hcat[:, 0:D] -------------
__global__ void transpose_hx_kernel(const float* __restrict__ Hx) {
    __shared__ float tile[32][33];
    int b  = blockIdx.z;
    int d0 = blockIdx.y * 32;
    int t0 = blockIdx.x * 32;
    #pragma unroll
    for (int yy = threadIdx.y; yy < 32; yy += 8)
        tile[yy][threadIdx.x] = Hx[((size_t)(b * D_ + d0 + yy)) * T_ + t0 + threadIdx.x];
    __syncthreads();
    #pragma unroll
    for (int yy = threadIdx.y; yy < 32; yy += 8)
        g_hcat[((size_t)(b * T_ + t0 + yy)) * D2_ + d0 + threadIdx.x] = tile[threadIdx.x][yy];
}

__global__ void copy_hf_kernel(const float4* __restrict__ Hf) {
    int idx = blockIdx.x * blockDim.x + threadIdx.x;
    if (idx >= B_ * T_ * (D_ / 4)) return;
    int row  = idx / (D_ / 4);
    int col4 = idx % (D_ / 4);
    float4 v = Hf[idx];
    *reinterpret_cast<float4*>(&g_hcat[(size_t)row * D2_ + D_ + col4 * 4]) = v;
}

// ---------------- tf32 GEMM: C[M,N] = A[M,K] @ W[N,K]^T + bias[N] -----------
// Block 128x128, BK=32, 128 threads = 4 warps (2m x 2n), warp tile 64x64.
// smem tiles stored [row][k] with LDK=36 words (144B rows): conflict-free
// fragment LDS (bank = 4g+tq) and 16B-aligned cp.async rows.
#define LDK   36
#define TILEW (128 * LDK)                         // words per tile
#define GEMM_SMEM (2 * 2 * TILEW * 4)             // 2 stages x (A,B) = 73728 B

__global__ void __launch_bounds__(128) gemm_tf32_cp_kernel(
    const float* __restrict__ A, int lda,
    const float* __restrict__ W,
    const float* __restrict__ bias,
    float* __restrict__ C, int ldc, int Kdim)
{
    extern __shared__ float sm[];
    const uint32_t sm_base = smem_u32(sm);

    const int tid  = threadIdx.x;
    const int lane = tid & 31;
    const int warp = tid >> 5;
    const int g    = lane >> 2;
    const int tq   = lane & 3;
    const int wm   = warp & 1;
    const int wn   = warp >> 1;
    const size_t mBase = (size_t)blockIdx.y * 128;
    const int    nBase = blockIdx.x * 128;

    const float* Ap = A + mBase * lda;
    const float* Wp = W + (size_t)nBase * Kdim;

    float acc[4][8][4];
    #pragma unroll
    for (int mt = 0; mt < 4; mt++)
        #pragma unroll
        for (int nt = 0; nt < 8; nt++)
            #pragma unroll
            for (int e = 0; e < 4; e++) acc[mt][nt][e] = 0.f;

    const int mrow = tid >> 3;          // 0..15 base row (stride 16 via j)
    const int kchk = (tid & 7) << 2;    // 0,4,...,28 (k word offset)

    // async tile loader: per thread 8 rows of A + 8 rows of B, 16B each
    auto load_tile = [&](int s, int k0) {
        uint32_t dA = sm_base + (uint32_t)(s * 2 * TILEW) * 4;
        uint32_t dB = dA + TILEW * 4;
        #pragma unroll
        for (int j = 0; j < 8; j++) {
            int m = mrow + 16 * j;
            cp_async16(dA + (uint32_t)(m * LDK + kchk) * 4,
                       Ap + (size_t)m * lda + k0 + kchk);
            cp_async16(dB + (uint32_t)(m * LDK + kchk) * 4,
                       Wp + (size_t)m * Kdim + k0 + kchk);
        }
        asm volatile("cp.async.commit_group;" ::: "memory");
    };

    const int niter = Kdim >> 5;

    load_tile(0, 0);

    for (int it = 0; it < niter; it++) {
        if (it + 1 < niter) {
            load_tile((it + 1) & 1, (it + 1) << 5);
            asm volatile("cp.async.wait_group 1;" ::: "memory");
        } else {
            asm volatile("cp.async.wait_group 0;" ::: "memory");
        }
        __syncthreads();

        const float* sA = sm + (it & 1) * 2 * TILEW;
        const float* sB = sA + TILEW;

        #pragma unroll
        for (int s = 0; s < 4; s++) {
            const int k = 8 * s;
            uint32_t af[4][4], bf[8][2];
            #pragma unroll
            for (int mt = 0; mt < 4; mt++) {
                int m0 = wm * 64 + mt * 16 + g;
                af[mt][0] = f2tf(sA[m0 * LDK + k + tq]);
                af[mt][1] = f2tf(sA[(m0 + 8) * LDK + k + tq]);
                af[mt][2] = f2tf(sA[m0 * LDK + k + tq + 4]);
                af[mt][3] = f2tf(sA[(m0 + 8) * LDK + k + tq + 4]);
            }
            #pragma unroll
            for (int nt = 0; nt < 8; nt++) {
                int n0 = wn * 64 + nt * 8 + g;
                bf[nt][0] = f2tf(sB[n0 * LDK + k + tq]);
                bf[nt][1] = f2tf(sB[n0 * LDK + k + tq + 4]);
            }
            #pragma unroll
            for (int mt = 0; mt < 4; mt++)
                #pragma unroll
                for (int nt = 0; nt < 8; nt++)
                    mma_tf32(acc[mt][nt], af[mt], bf[nt]);
        }
        __syncthreads();
    }

    // epilogue
    #pragma unroll
    for (int nt = 0; nt < 8; nt++) {
        int col = nBase + wn * 64 + nt * 8 + 2 * tq;
        float2 bv = *reinterpret_cast<const float2*>(&bias[col]);
        #pragma unroll
        for (int mt = 0; mt < 4; mt++) {
            size_t row = mBase + wm * 64 + mt * 16 + g;
            float2 v0 = make_float2(acc[mt][nt][0] + bv.x, acc[mt][nt][1] + bv.y);
            float2 v1 = make_float2(acc[mt][nt][2] + bv.x, acc[mt][nt][3] + bv.y);
            *reinterpret_cast<float2*>(&C[row * ldc + col])       = v0;
            *reinterpret_cast<float2*>(&C[(row + 8) * ldc + col]) = v1;
        }
    }
}

// ---------------- tf32 flash attention with additive bias (round 2) ---------
#define ALD 68
#define ATTN_SMEM ((3 * 64 * ALD + 4 * 16 * ALD) * (int)sizeof(uint32_t))

__global__ void __launch_bounds__(128) attn_tf32_kernel() {
    extern __shared__ uint32_t smu[];
    uint32_t* Qs = smu;
    uint32_t* Ks = smu + 64 * ALD;
    uint32_t* Vs = smu + 2 * 64 * ALD;
    uint32_t* Ps = smu + 3 * 64 * ALD;

    const int tid  = threadIdx.x;
    const int lane = tid & 31;
    const int warp = tid >> 5;
    const int g    = lane >> 2;
    const int tq   = lane & 3;
    const int b    = blockIdx.z;
    const int h    = blockIdx.y;
    const int q0   = blockIdx.x * 64;

    const float* __restrict__ Qg = g_Q + (size_t)b * T_ * D_ + (size_t)h * DK_;
    const float* __restrict__ Kg = g_K + (size_t)b * T_ * D_ + (size_t)h * DK_;
    const float* __restrict__ Vg = g_V + (size_t)b * T_ * D_ + (size_t)h * DK_;
    const float* __restrict__ Bg = g_bias + ((size_t)b * T_ + q0) * T_;

    #pragma unroll
    for (int i = tid; i < 64 * 16; i += 128) {
        int r = i >> 4, c4 = (i & 15) << 2;
        float4 v = *reinterpret_cast<const float4*>(&Qg[(size_t)(q0 + r) * D_ + c4]);
        Qs[r * ALD + c4 + 0] = f2tf(v.x);
        Qs[r * ALD + c4 + 1] = f2tf(v.y);
        Qs[r * ALD + c4 + 2] = f2tf(v.z);
        Qs[r * ALD + c4 + 3] = f2tf(v.w);
    }
    __syncthreads();

    uint32_t qa[8][4];
    {
        int base = (warp * 16 + g) * ALD;
        #pragma unroll
        for (int s = 0; s < 8; s++) {
            qa[s][0] = Qs[base + 8 * s + tq];
            qa[s][1] = Qs[base + 8 * ALD + 8 * s + tq];
            qa[s][2] = Qs[base + 8 * s + tq + 4];
            qa[s][3] = Qs[base + 8 * ALD + 8 * s + tq + 4];
        }
    }

    float o[8][4];
    #pragma unroll
    for (int nt = 0; nt < 8; nt++)
        #pragma unroll
        for (int e = 0; e < 4; e++) o[nt][e] = 0.f;
    float m0 = -CUDART_INF_F, m1 = -CUDART_INF_F, l0 = 0.f, l1 = 0.f;

    uint32_t* Pw = Ps + warp * 16 * ALD;

    for (int k0 = 0; k0 < T_; k0 += 64) {
        __syncthreads();
        #pragma unroll
        for (int i = tid; i < 64 * 16; i += 128) {
            int r = i >> 4, c4 = (i & 15) << 2;
            float4 kv = *reinterpret_cast<const float4*>(&Kg[(size_t)(k0 + r) * D_ + c4]);
            Ks[r * ALD + c4 + 0] = f2tf(kv.x);
            Ks[r * ALD + c4 + 1] = f2tf(kv.y);
            Ks[r * ALD + c4 + 2] = f2tf(kv.z);
            Ks[r * ALD + c4 + 3] = f2tf(kv.w);
            float4 vv = *reinterpret_cast<const float4*>(&Vg[(size_t)(k0 + r) * D_ + c4]);
            Vs[r * ALD + c4 + 0] = f2tf(vv.x);
            Vs[r * ALD + c4 + 1] = f2tf(vv.y);
            Vs[r * ALD + c4 + 2] = f2tf(vv.z);
            Vs[r * ALD + c4 + 3] = f2tf(vv.w);
        }
        __syncthreads();

        float sf[8][4];
        #pragma unroll
        for (int nt = 0; nt < 8; nt++) {
            sf[nt][0] = sf[nt][1] = sf[nt][2] = sf[nt][3] = 0.f;
            #pragma unroll
            for (int s = 0; s < 8; s++) {
                uint32_t bb[2];
                bb[0] = Ks[(nt * 8 + g) * ALD + 8 * s + tq];
                bb[1] = Ks[(nt * 8 + g) * ALD + 8 * s + tq + 4];
                mma_tf32(sf[nt], qa[s], bb);
            }
        }

        const float* Brow0 = Bg + (size_t)(warp * 16 + g) * T_ + k0;
        const float* Brow1 = Brow0 + 8 * T_;
        float mx0 = -CUDART_INF_F, mx1 = -CUDART_INF_F;
        #pragma unroll
        for (int nt = 0; nt < 8; nt++) {
            float2 b0v = *reinterpret_cast<const float2*>(&Brow0[nt * 8 + 2 * tq]);
            float2 b1v = *reinterpret_cast<const float2*>(&Brow1[nt * 8 + 2 * tq]);
            sf[nt][0] = fmaf(sf[nt][0], 0.125f, b0v.x);
            sf[nt][1] = fmaf(sf[nt][1], 0.125f, b0v.y);
            sf[nt][2] = fmaf(sf[nt][2], 0.125f, b1v.x);
            sf[nt][3] = fmaf(sf[nt][3], 0.125f, b1v.y);
            mx0 = fmaxf(mx0, fmaxf(sf[nt][0], sf[nt][1]));
            mx1 = fmaxf(mx1, fmaxf(sf[nt][2], sf[nt][3]));
        }
        mx0 = fmaxf(mx0, __shfl_xor_sync(0xffffffffu, mx0, 1));
        mx0 = fmaxf(mx0, __shfl_xor_sync(0xffffffffu, mx0, 2));
        mx1 = fmaxf(mx1, __shfl_xor_sync(0xffffffffu, mx1, 1));
        mx1 = fmaxf(mx1, __shfl_xor_sync(0xffffffffu, mx1, 2));

        float mn0 = fmaxf(m0, mx0), mn1 = fmaxf(m1, mx1);
        float c0 = __expf(m0 - mn0), c1 = __expf(m1 - mn1);
        float rs0 = 0.f, rs1 = 0.f;
        #pragma unroll
        for (int nt = 0; nt < 8; nt++) {
            float p0 = __expf(sf[nt][0] - mn0);
            float p1 = __expf(sf[nt][1] - mn0);
            float p2 = __expf(sf[nt][2] - mn1);
            float p3 = __expf(sf[nt][3] - mn1);
            rs0 += p0 + p1;
            rs1 += p2 + p3;
            uint2 u0 = make_uint2(f2tf(p0), f2tf(p1));
            uint2 u1 = make_uint2(f2tf(p2), f2tf(p3));
            *reinterpret_cast<uint2*>(&Pw[g * ALD + nt * 8 + 2 * tq])       = u0;
            *reinterpret_cast<uint2*>(&Pw[(g + 8) * ALD + nt * 8 + 2 * tq]) = u1;
        }
        rs0 += __shfl_xor_sync(0xffffffffu, rs0, 1);
        rs0 += __shfl_xor_sync(0xffffffffu, rs0, 2);
        rs1 += __shfl_xor_sync(0xffffffffu, rs1, 1);
        rs1 += __shfl_xor_sync(0xffffffffu, rs1, 2);
        l0 = l0 * c0 + rs0;
        l1 = l1 * c1 + rs1;
        m0 = mn0; m1 = mn1;
        #pragma unroll
        for (int nt = 0; nt < 8; nt++) {
            o[nt][0] *= c0; o[nt][1] *= c0;
            o[nt][2] *= c1; o[nt][3] *= c1;
        }
        __syncwarp();

        #pragma unroll
        for (int s = 0; s < 8; s++) {
            uint32_t pa[4];
            pa[0] = Pw[g * ALD + 8 * s + tq];
            pa[1] = Pw[(g + 8) * ALD + 8 * s + tq];
            pa[2] = Pw[g * ALD + 8 * s + tq + 4];
            pa[3] = Pw[(g + 8) * ALD + 8 * s + tq + 4];
            #pragma unroll
            for (int nt = 0; nt < 8; nt++) {
                uint32_t bb[2];
                bb[0] = Vs[(8 * s + tq) * ALD + nt * 8 + g];
                bb[1] = Vs[(8 * s + tq + 4) * ALD + nt * 8 + g];
                mma_tf32(o[nt], pa, bb);
            }
        }
        __syncwarp();
    }

    float inv0 = 1.0f / l0, inv1 = 1.0f / l1;
    float* Og = g_O + (size_t)b * T_ * D_ + (size_t)h * DK_;
    size_t r0 = (size_t)q0 + warp * 16 + g;
    #pragma unroll
    for (int nt = 0; nt < 8; nt++) {
        int col = nt * 8 + 2 * tq;
        float2 v0 = make_float2(o[nt][0] * inv0, o[nt][1] * inv0);
        float2 v1 = make_float2(o[nt][2] * inv1, o[nt][3] * inv1);
        *reinterpret_cast<float2*>(&Og[r0 * D_ + col])       = v0;
        *reinterpret_cast<float2*>(&Og[(r0 + 8) * D_ + col]) = v1;
    }
}

// ---------------- launch ----------------------------------------------------
extern "C" void kernel_launch(void* const* d_in, const int* in_sizes, int n_in,
                              void* d_out, int out_size) {
    const float* Hx = (const float*)d_in[0];
    const float* Hf = (const float*)d_in[1];
    const float* Gm = (const float*)d_in[2];
    const float* Wg = (const float*)d_in[3];
    const float* bg = (const float*)d_in[4];
    const float* Wq = (const float*)d_in[5];
    const float* bq = (const float*)d_in[6];
    const float* Wk = (const float*)d_in[7];
    const float* bk = (const float*)d_in[8];
    const float* Wv = (const float*)d_in[9];
    const float* bv = (const float*)d_in[10];
    const float* Wo = (const float*)d_in[11];
    const float* bo = (const float*)d_in[12];
    float* out = (float*)d_out;

    float *hcat, *Q, *K, *V, *bias, *O;
    cudaGetSymbolAddress((void**)&hcat, g_hcat);
    cudaGetSymbolAddress((void**)&Q,    g_Q);
    cudaGetSymbolAddress((void**)&K,    g_K);
    cudaGetSymbolAddress((void**)&V,    g_V);
    cudaGetSymbolAddress((void**)&bias, g_bias);
    cudaGetSymbolAddress((void**)&O,    g_O);

    cudaFuncSetAttribute(gemm_tf32_cp_kernel,
                         cudaFuncAttributeMaxDynamicSharedMemorySize, GEMM_SMEM);
    cudaFuncSetAttribute(attn_tf32_kernel,
                         cudaFuncAttributeMaxDynamicSharedMemorySize, ATTN_SMEM);

    // 1) build hcat = [hx | Hf]
    transpose_hx_kernel<<<dim3(T_ / 32, D_ / 32, B_), dim3(32, 8)>>>(Hx);
    copy_hf_kernel<<<(B_ * T_ * (D_ / 4) + 255) / 256, 256>>>((const float4*)Hf);

    // 2) projections: grid (N/128, M/128)
    gemm_tf32_cp_kernel<<<dim3(D_ / 128, 32), 128, GEMM_SMEM>>>(hcat, D2_, Wq, bq, Q, D_, D2_);
    gemm_tf32_cp_kernel<<<dim3(D_ / 128, 32), 128, GEMM_SMEM>>>(hcat, D2_, Wk, bk, K, D_, D2_);
    gemm_tf32_cp_kernel<<<dim3(D_ / 128, 32), 128, GEMM_SMEM>>>(hcat, D2_, Wv, bv, V, D_, D_);
    // 3) bias = Gm @ Wg^T + bg
    gemm_tf32_cp_kernel<<<dim3(T_ / 128, 32), 128, GEMM_SMEM>>>(Gm, DM_, Wg, bg, bias, T_, DM_);

    // 4) attention
    attn_tf32_kernel<<<dim3(T_ / 64, H_, B_), 128, ATTN_SMEM>>>();

    // 5) output projection
    gemm_tf32_cp_kernel<<<dim3(D_ / 128, 32), 128, GEMM_SMEM>>>(O, D_, Wo, bo, out, D_, D_);
}